// round 16
// baseline (speedup 1.0000x reference)
#include <cuda_runtime.h>
#include <cuda_bf16.h>
#include <cstdint>

typedef unsigned int u32;

#define M_SLOTS 60
#define CHANS   256
#define HW      3136           // 56*56
#define NTOT    802816         // 256*3136 elements per memory slot
#define BATCH   64
#define KPAD    64             // K padded to 64 (rows 60..63 of W are zero)
#define EPS     1e-8f

#define NTILE   64             // spatial floats per tile (3136/64=49 -> tile never straddles a channel)
#define SROW    72             // padded stage row (72 mod 32 = 8 -> conflict-free B-frags)
#define STAGEN  (64 * SROW)    // 4608 floats per stage buffer
#define NSTAGE  5
#define SMEM_BYTES (NSTAGE * STAGEN * 4)   // 92160 B -> exactly 2 CTAs/SM
#define NT      (NTOT / NTILE) // 12544 tiles
#define GRID    296            // 148 SMs * 2 CTAs -> all co-resident (barrier-safe)

// Scratch (device globals — no allocation allowed)
__device__ float g_mem_avg[M_SLOTS * CHANS];   // [m][c] channel SUMS (cosine is scale-invariant)
__device__ float g_wbm[BATCH * KPAD];          // [b][k] tf32-rounded weights, k>=60 zero
__device__ u32 g_count = 0;                    // barrier state (self-resetting)
__device__ u32 g_gen   = 0;

__device__ __forceinline__ u32 f2tf32(float x) {
    u32 r;
    asm("cvt.rna.tf32.f32 %0, %1;" : "=r"(r) : "f"(x));
    return r;
}

// L2-coherent, un-hoistable load for data WRITTEN DURING THIS KERNEL by other CTAs.
__device__ __forceinline__ float ldcg(const float* p) {
    float v;
    asm volatile("ld.global.cg.f32 %0, [%1];" : "=f"(v) : "l"(p));
    return v;
}

// Sense-reversing grid barrier. Safe: all GRID CTAs are co-resident by occupancy.
__device__ __forceinline__ void grid_barrier() {
    __syncthreads();
    if (threadIdx.x == 0) {
        __threadfence();                            // publish this CTA's prior writes
        u32 my  = atomicAdd(&g_gen, 0u);            // read generation BEFORE arriving
        u32 old = atomicAdd(&g_count, 1u);
        if (old == GRID - 1u) {
            atomicExch(&g_count, 0u);               // reset for next barrier
            __threadfence();
            atomicAdd(&g_gen, 1u);                  // release
        } else {
            while (atomicAdd(&g_gen, 0u) == my) __nanosleep(128);
        }
        __threadfence();
    }
    __syncthreads();
}

// zero the channel-sum accumulator (must be re-zeroed every call, deterministically)
__global__ void zero_kernel() {
    int i = blockIdx.x * 256 + threadIdx.x;
    if (i < M_SLOTS * CHANS) g_mem_avg[i] = 0.0f;
}

// ---------------- fused persistent kernel ----------------
__global__ __launch_bounds__(256, 2) void fused_kernel(const float* __restrict__ mem,
                                                       const float* __restrict__ q,
                                                       float* __restrict__ out) {
    extern __shared__ float stage[];   // NSTAGE * STAGEN
    __shared__ float s_cos[M_SLOTS];
    __shared__ float s_qn;

    const int tid  = threadIdx.x;
    const int lane = tid & 31;
    const int wrp  = tid >> 5;
    const int mpair = wrp & 1;
    const int nquad = wrp >> 1;
    const int g = lane >> 2, t = lane & 3;

    const int qq = NT / GRID, rr = NT % GRID;          // 42, 112
    const int bid = blockIdx.x;
    const int len  = qq + (bid < rr ? 1 : 0);
    const int base = bid * qq + (bid < rr ? bid : rr);

    const u32 sbase = (u32)__cvta_generic_to_shared(stage);

    // zero k-pad rows 60..63 of all stage buffers
    for (int j = tid; j < NSTAGE * 4 * SROW; j += 256) {
        int s = j / (4 * SROW);
        int rem = j % (4 * SROW);
        stage[s * STAGEN + (60 + rem / SROW) * SROW + (rem % SROW)] = 0.0f;
    }

    // ===== phase 1: per-strip channel partial SUMS =====
    // Branch-free streaming inner loop per channel segment (<=3 segments/strip).
    // j = tid + i*256 < 960: unconditional for i=0..2, predicated only for i=3.
    {
        int tcur = base;
        const int tend = base + len;
        while (tcur < tend) {
            const int c = tcur / 49;                               // channel of this segment
            const int seg_end = min((c + 1) * 49, tend);
            float acc[4] = {0.0f, 0.0f, 0.0f, 0.0f};
            for (int tix = tcur; tix < seg_end; tix++) {
                const size_t n0 = (size_t)tix * NTILE;
#pragma unroll
                for (int i = 0; i < 4; i++) {
                    int j = tid + i * 256;
                    if (j < 960) {
                        int row = j >> 4, col = (j & 15) << 2;
                        float4 v = __ldcs((const float4*)(mem + (size_t)row * NTOT + n0 + col));
                        acc[i] += (v.x + v.y) + (v.z + v.w);
                    }
                }
            }
#pragma unroll
            for (int i = 0; i < 4; i++) {
                float s = acc[i];
#pragma unroll
                for (int o = 8; o > 0; o >>= 1)
                    s += __shfl_xor_sync(0xffffffffu, s, o, 16);   // reduce 16-lane group
                int j = tid + i * 256;
                if (j < 960 && (lane & 15) == 0)
                    atomicAdd(&g_mem_avg[(j >> 4) * CHANS + c], s);
            }
            tcur = seg_end;
        }
    }

    // ---- early prefetch of first phase-3 tiles (REVERSE order; independent of weights) ----
    auto tile_of = [&](int u) { return base + (len - 1 - u); };
    auto load_tile = [&](int u) {
        const int bsel = u % NSTAGE;
        const size_t n0 = (size_t)tile_of(u) * NTILE;
#pragma unroll
        for (int i = 0; i < 4; i++) {
            int j = tid + i * 256;
            if (j < 960) {
                int row = j >> 4, col = (j & 15) << 2;
                u32 dst = sbase + (u32)((bsel * STAGEN + row * SROW + col) * 4);
                const float* src = mem + (size_t)row * NTOT + n0 + col;
                asm volatile("cp.async.cg.shared.global [%0], [%1], 16;\n"
                             :: "r"(dst), "l"(src));
            }
        }
    };
#pragma unroll
    for (int pf = 0; pf < NSTAGE - 1; pf++) {          // preload 4 tiles (strip tail = L2-hot)
        if (pf < len) load_tile(pf);
        asm volatile("cp.async.commit_group;\n" ::: "memory");
    }

    grid_barrier();   // all channel sums visible

    // ===== phase 2: weights (CTAs 0..63, one batch each) =====
    if (bid < BATCH) {
        const int b = bid;
        if (wrp == 0) {
            float s = 0.0f;
            const float* qr = q + b * CHANS;
            for (int i = lane; i < CHANS; i += 32) { float v = qr[i]; s += v * v; }
            for (int o = 16; o > 0; o >>= 1) s += __shfl_xor_sync(0xffffffffu, s, o);
            if (lane == 0) s_qn = sqrtf(s);
        }
        __syncthreads();
        const float qn = fmaxf(s_qn, EPS);

        for (int m = wrp; m < M_SLOTS; m += 8) {
            const float* mr = g_mem_avg + m * CHANS;   // SUMS, written by atomics this kernel
            const float* qr = q + b * CHANS;
            float dot = 0.0f, mn2 = 0.0f;
            for (int i = lane; i < CHANS; i += 32) {
                float mv = ldcg(mr + i);               // L2-coherent read
                dot = fmaf(mv, qr[i], dot);
                mn2 = fmaf(mv, mv, mn2);
            }
            for (int o = 16; o > 0; o >>= 1) {
                dot += __shfl_xor_sync(0xffffffffu, dot, o);
                mn2 += __shfl_xor_sync(0xffffffffu, mn2, o);
            }
            if (lane == 0) s_cos[m] = dot / (qn * fmaxf(sqrtf(mn2), EPS));
        }
        __syncthreads();

        if (wrp == 0) {
            float v0 = (lane < M_SLOTS) ? s_cos[lane] : -1e30f;
            float v1 = (lane + 32 < M_SLOTS) ? s_cos[lane + 32] : -1e30f;
            float mx = fmaxf(v0, v1);
            for (int o = 16; o > 0; o >>= 1) mx = fmaxf(mx, __shfl_xor_sync(0xffffffffu, mx, o));
            float e0 = (lane < M_SLOTS) ? expf(v0 - mx) : 0.0f;
            float e1 = (lane + 32 < M_SLOTS) ? expf(v1 - mx) : 0.0f;
            float sm = e0 + e1;
            for (int o = 16; o > 0; o >>= 1) sm += __shfl_xor_sync(0xffffffffu, sm, o);
            float inv = 1.0f / sm;
            if (lane < M_SLOTS)
                g_wbm[b * KPAD + lane] = __uint_as_float(f2tf32(e0 * inv));
            if (lane + 32 < M_SLOTS)
                g_wbm[b * KPAD + lane + 32] = __uint_as_float(f2tf32(e1 * inv));
            if (lane < KPAD - M_SLOTS)
                g_wbm[b * KPAD + M_SLOTS + lane] = 0.0f;
        }
    }

    grid_barrier();   // g_wbm ready everywhere

    // ===== phase 3: einsum, tiles in REVERSE order (harvest phase-1 L2 tail) =====
    // A fragments from g_wbm via ld.global.cg (coherent, cannot be hoisted above barrier)
    float4 a[2][8];
#pragma unroll
    for (int mi = 0; mi < 2; mi++) {
        const int m0 = (mpair * 2 + mi) * 16;
#pragma unroll
        for (int kk = 0; kk < 8; kk++) {
            const int k = kk * 8 + t;
            a[mi][kk] = make_float4(ldcg(g_wbm + (m0 + g)     * KPAD + k),
                                    ldcg(g_wbm + (m0 + g + 8) * KPAD + k),
                                    ldcg(g_wbm + (m0 + g)     * KPAD + k + 4),
                                    ldcg(g_wbm + (m0 + g + 8) * KPAD + k + 4));
        }
    }

    for (int u = 0; u < len; u++) {
        asm volatile("cp.async.wait_group %0;\n" :: "n"(NSTAGE - 2) : "memory");
        __syncthreads();   // tile u arrived + prev epilogue reads of reused buffer done

        if (u + NSTAGE - 1 < len) load_tile(u + NSTAGE - 1);
        asm volatile("cp.async.commit_group;\n" ::: "memory");

        float* tp = stage + (u % NSTAGE) * STAGEN;
        const size_t n0 = (size_t)tile_of(u) * NTILE;

        float c[2][2][4];
#pragma unroll
        for (int mi = 0; mi < 2; mi++)
#pragma unroll
            for (int ni = 0; ni < 2; ni++)
#pragma unroll
                for (int r = 0; r < 4; r++) c[mi][ni][r] = 0.0f;

#pragma unroll
        for (int kk = 0; kk < 8; kk++) {
            const float* r0 = tp + (kk * 8 + t) * SROW + nquad * 16 + g;
            const float* r1 = r0 + 4 * SROW;
            u32 b0[2], b1[2];
#pragma unroll
            for (int ni = 0; ni < 2; ni++) {
                b0[ni] = f2tf32(r0[ni * 8]);
                b1[ni] = f2tf32(r1[ni * 8]);
            }
#pragma unroll
            for (int mi = 0; mi < 2; mi++) {
                u32 a0 = __float_as_uint(a[mi][kk].x), a1 = __float_as_uint(a[mi][kk].y);
                u32 a2 = __float_as_uint(a[mi][kk].z), a3 = __float_as_uint(a[mi][kk].w);
#pragma unroll
                for (int ni = 0; ni < 2; ni++) {
                    asm volatile(
                        "mma.sync.aligned.m16n8k8.row.col.f32.tf32.tf32.f32 "
                        "{%0,%1,%2,%3}, {%4,%5,%6,%7}, {%8,%9}, {%0,%1,%2,%3};"
                        : "+f"(c[mi][ni][0]), "+f"(c[mi][ni][1]),
                          "+f"(c[mi][ni][2]), "+f"(c[mi][ni][3])
                        : "r"(a0), "r"(a1), "r"(a2), "r"(a3),
                          "r"(b0[ni]), "r"(b1[ni]));
                }
            }
        }
        __syncthreads();   // all warps done reading stage[u%NSTAGE] -> reuse as obuf

        // ---- transposed epilogue through the just-consumed stage buffer ----
        {
#pragma unroll
            for (int mi = 0; mi < 2; mi++) {
                float* ob = tp + (mpair * 32 + mi * 16 + g) * SROW + nquad * 16 + t * 2;
#pragma unroll
                for (int ni = 0; ni < 2; ni++) {
                    *(float2*)(ob + ni * 8)            = make_float2(c[mi][ni][0], c[mi][ni][1]);
                    *(float2*)(ob + ni * 8 + 8 * SROW) = make_float2(c[mi][ni][2], c[mi][ni][3]);
                }
            }
        }
        __syncthreads();

        // coalesced read + STG.128: thread -> 4 batch rows, 16B chunk each
        {
            const int c4 = (tid & 15) * 4;
            const int r0w = tid >> 4;
#pragma unroll
            for (int i = 0; i < 4; i++) {
                int r = r0w + i * 16;
                float4 v = *(float4*)(tp + r * SROW + c4);
                *(float4*)(out + (size_t)r * NTOT + n0 + c4) = v;
            }
        }
    }
}

// ---------------- launcher ----------------
extern "C" void kernel_launch(void* const* d_in, const int* in_sizes, int n_in,
                              void* d_out, int out_size) {
    const float* mem = (const float*)d_in[0];
    const float* q   = (const float*)d_in[1];
    if (n_in >= 2 && in_sizes[0] < in_sizes[1]) {
        const float* t = mem; mem = q; q = t;
    }
    float* out = (float*)d_out;

    cudaFuncSetAttribute(fused_kernel,
                         cudaFuncAttributeMaxDynamicSharedMemorySize, SMEM_BYTES);

    zero_kernel<<<(M_SLOTS * CHANS + 255) / 256, 256>>>();
    fused_kernel<<<GRID, 256, SMEM_BYTES>>>(mem, q, out);
}

// round 17
// speedup vs baseline: 1.3715x; 1.3715x over previous
#include <cuda_runtime.h>
#include <cuda_bf16.h>
#include <cstdint>

typedef unsigned int u32;

#define M_SLOTS 60
#define CHANS   256
#define HW      3136           // 56*56
#define NTOT    802816         // 256*3136 elements per memory slot
#define BATCH   64
#define KPAD    64             // K padded to 64 (rows 60..63 of W are zero)
#define EPS     1e-8f

#define NTILE   64             // spatial floats per tile
#define SROW    72             // padded stage row (72 mod 32 = 8 -> conflict-free B-frags)
#define STAGEN  (64 * SROW)    // 4608 floats per stage buffer
#define NSTAGE  5
#define SMEM_BYTES (NSTAGE * STAGEN * 4)   // 92160 B -> 2 CTAs/SM = 184.3 KB, safe
#define NT      (NTOT / NTILE) // 12544 tiles
#define GRID    296            // 148 SMs * 2 CTAs

// Scratch (device globals — no allocation allowed)
__device__ float g_mem_avg[M_SLOTS * CHANS];   // [m][c]
// A fragments, warp-coalesced: [mtile(4)][kk(8)][lane(32)][r(4)]
// (written DIRECTLY by weights_kernel; pack_kernel eliminated)
__device__ float g_wA[4 * 8 * 32 * 4];

__device__ __forceinline__ u32 f2tf32(float x) {
    u32 r;
    asm("cvt.rna.tf32.f32 %0, %1;" : "=r"(r) : "f"(x));
    return r;
}

// ---------------- kernel 1: mean over H,W ----------------
// Warp-per-row, shfl-only. __ldcs + unroll 8 = best measured config (31.9us).
__global__ __launch_bounds__(256) void mean_kernel(const float* __restrict__ mem) {
    const int wrp  = threadIdx.x >> 5;
    const int lane = threadIdx.x & 31;
    const int r = blockIdx.x * 8 + wrp;                       // 0..15359
    const float4* p = (const float4*)(mem + (size_t)r * HW);  // 784 float4 per row
    float s = 0.0f;
#pragma unroll 8
    for (int i = lane; i < 784; i += 32) {
        float4 v = __ldcs(p + i);
        s += (v.x + v.y) + (v.z + v.w);
    }
#pragma unroll
    for (int o = 16; o > 0; o >>= 1) s += __shfl_xor_sync(0xffffffffu, s, o);
    if (lane == 0) g_mem_avg[r] = s * (1.0f / (float)HW);
}

// ---------------- kernel 2: cosine sim + softmax -> tf32 A-fragments ----------------
// One block per batch b. Scatters its 64 weights straight into g_wA's MMA
// fragment layout (mapping verified against the old pack_kernel term-by-term):
//   b -> mtile=b>>4, row=b&15 -> g=row&7, rbase=row>>3
//   k -> kk=k>>3, tt=k&7 -> t=tt&3, hi4=tt>>2;  r = 2*hi4 + rbase
//   float index = ((mtile*8+kk)*32 + g*4+t)*4 + r
// Lanes 28..31's k=lane+32 in [60,64) carry e1=0 -> zero pad preserved.
__global__ void weights_kernel(const float* __restrict__ q) {
    const int b = blockIdx.x;
    const int tid = threadIdx.x;
    const int lane = tid & 31;
    const int wrp = tid >> 5;

    __shared__ float s_cos[M_SLOTS];
    __shared__ float s_qn;

    if (wrp == 0) {
        float s = 0.0f;
        const float* qr = q + b * CHANS;
        for (int i = lane; i < CHANS; i += 32) { float v = qr[i]; s += v * v; }
        for (int o = 16; o > 0; o >>= 1) s += __shfl_xor_sync(0xffffffffu, s, o);
        if (lane == 0) s_qn = sqrtf(s);
    }
    __syncthreads();
    const float qn = fmaxf(s_qn, EPS);

    for (int m = wrp; m < M_SLOTS; m += 8) {
        const float* mr = g_mem_avg + m * CHANS;
        const float* qr = q + b * CHANS;
        float dot = 0.0f, mn2 = 0.0f;
        for (int i = lane; i < CHANS; i += 32) {
            float mv = mr[i];
            dot = fmaf(mv, qr[i], dot);
            mn2 = fmaf(mv, mv, mn2);
        }
        for (int o = 16; o > 0; o >>= 1) {
            dot += __shfl_xor_sync(0xffffffffu, dot, o);
            mn2 += __shfl_xor_sync(0xffffffffu, mn2, o);
        }
        if (lane == 0) s_cos[m] = dot / (qn * fmaxf(sqrtf(mn2), EPS));
    }
    __syncthreads();

    if (wrp == 0) {
        float v0 = (lane < M_SLOTS) ? s_cos[lane] : -1e30f;
        float v1 = (lane + 32 < M_SLOTS) ? s_cos[lane + 32] : -1e30f;
        float mx = fmaxf(v0, v1);
        for (int o = 16; o > 0; o >>= 1) mx = fmaxf(mx, __shfl_xor_sync(0xffffffffu, mx, o));
        float e0 = (lane < M_SLOTS) ? expf(v0 - mx) : 0.0f;
        float e1 = (lane + 32 < M_SLOTS) ? expf(v1 - mx) : 0.0f;
        float sm = e0 + e1;
        for (int o = 16; o > 0; o >>= 1) sm += __shfl_xor_sync(0xffffffffu, sm, o);
        const float inv = 1.0f / sm;

        const int mtile = b >> 4;
        const int row   = b & 15;
        const int gg    = row & 7;
        const int rbase = row >> 3;
        // k0 = lane (always < 60 since lane < 32)
        {
            const int k = lane;
            const int kk = k >> 3, tt = k & 7;
            const int r = ((tt >> 2) << 1) + rbase;
            g_wA[(((mtile * 8 + kk) * 32) + gg * 4 + (tt & 3)) * 4 + r] =
                __uint_as_float(f2tf32(e0 * inv));
        }
        // k1 = lane + 32 (>= 60 -> e1 == 0 -> writes the required zero pad)
        {
            const int k = lane + 32;
            const int kk = k >> 3, tt = k & 7;
            const int r = ((tt >> 2) << 1) + rbase;
            const float w = (k < M_SLOTS) ? e1 * inv : 0.0f;
            g_wA[(((mtile * 8 + kk) * 32) + gg * 4 + (tt & 3)) * 4 + r] =
                __uint_as_float(f2tf32(w));
        }
    }
}

// ---------------- kernel 3: einsum, 5-stage ring, 2 m-tiles/warp, REVERSE walk ----------------
// Warp = (mpair[2] x nquad[4]): m rows [mpair*32,+32), n cols [nquad*16,+16).
// Strips walked tail-first: mean_kernel's last-read ~126MB is still L2-resident
// when this launch starts (L2 survives launch boundaries; L1 does not).
__global__ __launch_bounds__(256, 2) void einsum_kernel(const float* __restrict__ mem,
                                                        float* __restrict__ out) {
    extern __shared__ float stage[];   // NSTAGE * STAGEN

    const int tid  = threadIdx.x;
    const int lane = tid & 31;
    const int wrp  = tid >> 5;
    const int mpair = wrp & 1;
    const int nquad = wrp >> 1;
    const int g = lane >> 2, t = lane & 3;

    const int qq = NT / GRID, rr = NT % GRID;          // 42, 112
    const int bid = blockIdx.x;
    const int len  = qq + (bid < rr ? 1 : 0);
    const int base = bid * qq + (bid < rr ? bid : rr);

    const u32 sbase = (u32)__cvta_generic_to_shared(stage);

    // zero k-pad rows 60..63 of all stage buffers
    for (int j = tid; j < NSTAGE * 4 * SROW; j += 256) {
        int s = j / (4 * SROW);
        int rem = j % (4 * SROW);
        stage[s * STAGEN + (60 + rem / SROW) * SROW + (rem % SROW)] = 0.0f;
    }

    // reverse mapping: u-th processed tile is the (len-1-u)-th of the strip
    auto tile_of = [&](int u) { return base + (len - 1 - u); };

    // stage loader: 60 rows x 16 chunks of 16B = 960 chunks
    auto load_tile = [&](int u) {
        const int bsel = u % NSTAGE;
        const size_t n0 = (size_t)tile_of(u) * NTILE;
#pragma unroll
        for (int i = 0; i < 4; i++) {
            int j = tid + i * 256;
            if (j < 960) {
                int row = j >> 4, c = (j & 15) << 2;
                u32 dst = sbase + (u32)((bsel * STAGEN + row * SROW + c) * 4);
                const float* src = mem + (size_t)row * NTOT + n0 + c;
                asm volatile("cp.async.cg.shared.global [%0], [%1], 16;\n"
                             :: "r"(dst), "l"(src));
            }
        }
    };

#pragma unroll
    for (int pf = 0; pf < NSTAGE - 1; pf++) {          // preload 4 tiles (strip tail, L2-warm)
        if (pf < len) load_tile(pf);
        asm volatile("cp.async.commit_group;\n" ::: "memory");
    }

    // ---- hoisted A fragments: 2 m-tiles x 8 kk x 4 regs = 64 regs ----
    float4 a[2][8];
#pragma unroll
    for (int mi = 0; mi < 2; mi++) {
        const float4* ap = (const float4*)g_wA + ((mpair * 2 + mi) * 8) * 32 + lane;
#pragma unroll
        for (int kk = 0; kk < 8; kk++) a[mi][kk] = __ldg(ap + kk * 32);
    }

    for (int u = 0; u < len; u++) {
        asm volatile("cp.async.wait_group %0;\n" :: "n"(NSTAGE - 2) : "memory");
        __syncthreads();   // tile u arrived + prev epilogue reads of this buffer done

        if (u + NSTAGE - 1 < len) load_tile(u + NSTAGE - 1);
        asm volatile("cp.async.commit_group;\n" ::: "memory");

        float* tp = stage + (u % NSTAGE) * STAGEN;
        const size_t n0 = (size_t)tile_of(u) * NTILE;

        float c[2][2][4];
#pragma unroll
        for (int mi = 0; mi < 2; mi++)
#pragma unroll
            for (int ni = 0; ni < 2; ni++)
#pragma unroll
                for (int r = 0; r < 4; r++) c[mi][ni][r] = 0.0f;

#pragma unroll
        for (int kk = 0; kk < 8; kk++) {
            const float* r0 = tp + (kk * 8 + t) * SROW + nquad * 16 + g;
            const float* r1 = r0 + 4 * SROW;
            u32 b0[2], b1[2];
#pragma unroll
            for (int ni = 0; ni < 2; ni++) {
                b0[ni] = f2tf32(r0[ni * 8]);
                b1[ni] = f2tf32(r1[ni * 8]);
            }
#pragma unroll
            for (int mi = 0; mi < 2; mi++) {
                u32 a0 = __float_as_uint(a[mi][kk].x), a1 = __float_as_uint(a[mi][kk].y);
                u32 a2 = __float_as_uint(a[mi][kk].z), a3 = __float_as_uint(a[mi][kk].w);
#pragma unroll
                for (int ni = 0; ni < 2; ni++) {
                    asm volatile(
                        "mma.sync.aligned.m16n8k8.row.col.f32.tf32.tf32.f32 "
                        "{%0,%1,%2,%3}, {%4,%5,%6,%7}, {%8,%9}, {%0,%1,%2,%3};"
                        : "+f"(c[mi][ni][0]), "+f"(c[mi][ni][1]),
                          "+f"(c[mi][ni][2]), "+f"(c[mi][ni][3])
                        : "r"(a0), "r"(a1), "r"(a2), "r"(a3),
                          "r"(b0[ni]), "r"(b1[ni]));
                }
            }
        }
        __syncthreads();   // all warps done reading stage[u%NSTAGE] -> reuse as obuf

        // ---- transposed epilogue through the just-consumed stage buffer ----
        // (k-pad rows get finite output data on reuse; zero weight rows nullify them)
        {
#pragma unroll
            for (int mi = 0; mi < 2; mi++) {
                float* ob = tp + (mpair * 32 + mi * 16 + g) * SROW + nquad * 16 + t * 2;
#pragma unroll
                for (int ni = 0; ni < 2; ni++) {
                    *(float2*)(ob + ni * 8)            = make_float2(c[mi][ni][0], c[mi][ni][1]);
                    *(float2*)(ob + ni * 8 + 8 * SROW) = make_float2(c[mi][ni][2], c[mi][ni][3]);
                }
            }
        }
        __syncthreads();

        // coalesced read + STG.128: thread -> 4 batch rows, 16B chunk each
        {
            const int c4 = (tid & 15) * 4;
            const int r0w = tid >> 4;
#pragma unroll
            for (int i = 0; i < 4; i++) {
                int r = r0w + i * 16;
                float4 v = *(float4*)(tp + r * SROW + c4);
                *(float4*)(out + (size_t)r * NTOT + n0 + c4) = v;
            }
        }
        // loop-top wait+sync protects stage[u%NSTAGE] (next written by tile u+NSTAGE,
        // prefetched at iteration u+1 after its own loop-top sync)
    }
}

// ---------------- launcher ----------------
extern "C" void kernel_launch(void* const* d_in, const int* in_sizes, int n_in,
                              void* d_out, int out_size) {
    const float* mem = (const float*)d_in[0];
    const float* q   = (const float*)d_in[1];
    if (n_in >= 2 && in_sizes[0] < in_sizes[1]) {
        const float* t = mem; mem = q; q = t;
    }
    float* out = (float*)d_out;

    cudaFuncSetAttribute(einsum_kernel,
                         cudaFuncAttributeMaxDynamicSharedMemorySize, SMEM_BYTES);

    mean_kernel<<<M_SLOTS * CHANS / 8, 256>>>(mem);
    weights_kernel<<<BATCH, 256>>>(q);
    einsum_kernel<<<GRID, 256, SMEM_BYTES>>>(mem, out);
}